// round 7
// baseline (speedup 1.0000x reference)
#include <cuda_runtime.h>
#include <cuda_bf16.h>
#include <cstddef>
#include <cstdint>

#define NUM_CLASS 1000
#define DIMS      2048
#define HEADSZ    256
#define NSAMP     16384
#define ALPHA_F   0.999f

#define SAMPLES_PER_BLOCK 8
#define NPAIRS (SAMPLES_PER_BLOCK / 2)             // 4
#define NLOSS_BLOCKS (NSAMP / SAMPLES_PER_BLOCK)   // 2048

// Scratch (__device__ globals; zero-init is the valid empty state, and the
// kernels self-reset everything for the next graph replay).
__device__ int    g_last_idx[NUM_CLASS];   // stores sample_index+1; 0 = empty
__device__ double g_loss_accum;
__device__ int    g_ticket;

// ---------------------------------------------------------------------------
// Kernel A: last-write-wins index per class, from labels only (64 KB read).
// ---------------------------------------------------------------------------
__global__ __launch_bounds__(512) void ema_lastidx_kernel(
    const int* __restrict__ labels)
{
    const int n = blockIdx.x * 512 + threadIdx.x;
    if (n < NSAMP) {
        atomicMax(&g_last_idx[labels[n]], n + 1);
    }
}

// ---------------------------------------------------------------------------
// Kernel B (fused):
//   blocks [0, NUM_CLASS)            : EMA scatter update (one class each)
//   blocks [NUM_CLASS, +NLOSS_BLOCKS): SSE for 8 samples
// Loss path stages the x stream in SMEM via cp.async.cg (2-stage pipeline,
// 16 KB/stage). Each thread async-copies exactly the bytes it later reads, so
// the pipeline needs no __syncthreads. Registers stay low -> high occupancy
// AND deep in-flight bytes (the R4-R6 tradeoff eliminated).
// ---------------------------------------------------------------------------
__global__ __launch_bounds__(256, 6) void ema_fused_kernel(
    const float* __restrict__ x,
    const int*   __restrict__ labels,
    const float* __restrict__ centers,
    float*       __restrict__ out_loss,      // may be null
    float*       __restrict__ out_centers)
{
    __shared__ float4 xs[2][2][512];   // [stage][sample-in-pair][float4 idx] = 32 KB
    __shared__ float  warp_s[8];

    const int b = blockIdx.x;
    const int t = threadIdx.x;

    if (b < NUM_CLASS) {
        // ---------------- update path: one class per block ----------------
        const int c       = b;
        const int last_p1 = g_last_idx[c];   // final: kernel A completed

        const float4* __restrict__ cr = reinterpret_cast<const float4*>(centers + (size_t)c * DIMS);
        float* __restrict__ oc = out_centers + (size_t)c * DIMS;

        if (last_p1 > 0) {
            const float4* __restrict__ xr =
                reinterpret_cast<const float4*>(x + (size_t)(last_p1 - 1) * DIMS);
            const float beta = 1.0f - ALPHA_F;
            const float4 cv0 = cr[t];
            const float4 cv1 = cr[t + 256];
            const float4 xv0 = __ldcs(&xr[t]);
            const float4 xv1 = __ldcs(&xr[t + 256]);
            const int base = t * 4;
            __stcs(&oc[base + 0], ALPHA_F * cv0.x + beta * xv0.x);
            __stcs(&oc[base + 1], ALPHA_F * cv0.y + beta * xv0.y);
            __stcs(&oc[base + 2], ALPHA_F * cv0.z + beta * xv0.z);
            __stcs(&oc[base + 3], ALPHA_F * cv0.w + beta * xv0.w);
            __stcs(&oc[base + 1024], ALPHA_F * cv1.x + beta * xv1.x);
            __stcs(&oc[base + 1025], ALPHA_F * cv1.y + beta * xv1.y);
            __stcs(&oc[base + 1026], ALPHA_F * cv1.z + beta * xv1.z);
            __stcs(&oc[base + 1027], ALPHA_F * cv1.w + beta * xv1.w);
        } else {
            const float4 cv0 = cr[t];
            const float4 cv1 = cr[t + 256];
            const int base = t * 4;
            __stcs(&oc[base + 0], cv0.x);
            __stcs(&oc[base + 1], cv0.y);
            __stcs(&oc[base + 2], cv0.z);
            __stcs(&oc[base + 3], cv0.w);
            __stcs(&oc[base + 1024], cv1.x);
            __stcs(&oc[base + 1025], cv1.y);
            __stcs(&oc[base + 1026], cv1.z);
            __stcs(&oc[base + 1027], cv1.w);
        }

        __syncthreads();
        if (t == 0) g_last_idx[c] = 0;   // self-reset for next replay
        return;
    }

    // ------- loss path: 8 samples, 4 pairs, cp.async 2-stage pipeline -------
    const int bi   = b - NUM_CLASS;
    const int base = bi * SAMPLES_PER_BLOCK;
    const int2* __restrict__ lp = reinterpret_cast<const int2*>(labels + base);

    // Per-thread smem targets (each thread copies exactly what it reads back).
    const uint32_t s00 = (uint32_t)__cvta_generic_to_shared(&xs[0][0][t]);
    const uint32_t s01 = (uint32_t)__cvta_generic_to_shared(&xs[0][0][t + 256]);
    const uint32_t s02 = (uint32_t)__cvta_generic_to_shared(&xs[0][1][t]);
    const uint32_t s03 = (uint32_t)__cvta_generic_to_shared(&xs[0][1][t + 256]);
    const uint32_t stage_stride =
        (uint32_t)((char*)&xs[1][0][0] - (char*)&xs[0][0][0]);

#define CP16(dst, src) \
    asm volatile("cp.async.cg.shared.global [%0], [%1], 16;" :: "r"(dst), "l"(src))
#define CP_COMMIT()  asm volatile("cp.async.commit_group;" ::: "memory")
#define CP_WAIT(n)   asm volatile("cp.async.wait_group %0;" :: "n"(n) : "memory")

#define ISSUE_PAIR(p, stage)                                                     \
    do {                                                                         \
        const float4* __restrict__ xr0 =                                         \
            reinterpret_cast<const float4*>(x + (size_t)(base + 2 * (p)) * DIMS);\
        const float4* __restrict__ xr1 =                                         \
            reinterpret_cast<const float4*>(x + (size_t)(base + 2 * (p) + 1) * DIMS);\
        const uint32_t so = (stage) * stage_stride;                              \
        CP16(s00 + so, xr0 + t);                                                 \
        CP16(s01 + so, xr0 + t + 256);                                           \
        CP16(s02 + so, xr1 + t);                                                 \
        CP16(s03 + so, xr1 + t + 256);                                           \
        CP_COMMIT();                                                             \
    } while (0)

#define SQD(a, b)                                                                \
    ((a.x - b.x) * (a.x - b.x) + (a.y - b.y) * (a.y - b.y) +                     \
     (a.z - b.z) * (a.z - b.z) + (a.w - b.w) * (a.w - b.w))

    float s = 0.0f;
    ISSUE_PAIR(0, 0);
    ISSUE_PAIR(1, 1);

#pragma unroll
    for (int p = 0; p < NPAIRS; ++p) {
        const int st = p & 1;
        if (p < NPAIRS - 1) { CP_WAIT(1); } else { CP_WAIT(0); }

        // Center rows: L2-resident, loaded just-in-time.
        const int2 L = lp[p];
        const float4* __restrict__ cr0 =
            reinterpret_cast<const float4*>(centers + (size_t)L.x * DIMS);
        const float4* __restrict__ cr1 =
            reinterpret_cast<const float4*>(centers + (size_t)L.y * DIMS);
        const float4 c0 = cr0[t];
        const float4 c1 = cr0[t + 256];
        const float4 c2 = cr1[t];
        const float4 c3 = cr1[t + 256];

        const float4 x0 = xs[st][0][t];
        const float4 x1 = xs[st][0][t + 256];
        const float4 x2 = xs[st][1][t];
        const float4 x3 = xs[st][1][t + 256];

        s += SQD(x0, c0);
        s += SQD(x1, c1);
        s += SQD(x2, c2);
        s += SQD(x3, c3);

        if (p + 2 < NPAIRS) {
            ISSUE_PAIR(p + 2, st);   // refill the stage we just drained
        }
    }
#undef ISSUE_PAIR
#undef SQD
#undef CP16
#undef CP_COMMIT
#undef CP_WAIT

    // warp reduce
#pragma unroll
    for (int o = 16; o > 0; o >>= 1) s += __shfl_xor_sync(0xFFFFFFFFu, s, o);

    if ((t & 31) == 0) warp_s[t >> 5] = s;
    __syncthreads();

    if (t == 0) {
        float v = warp_s[0] + warp_s[1] + warp_s[2] + warp_s[3]
                + warp_s[4] + warp_s[5] + warp_s[6] + warp_s[7];
        atomicAdd(&g_loss_accum, (double)v);
        __threadfence();
        const int old = atomicAdd(&g_ticket, 1);
        if (old == NLOSS_BLOCKS - 1) {
            if (out_loss != nullptr) {
                *out_loss = (float)(g_loss_accum / ((double)NSAMP * (double)HEADSZ));
            }
            g_loss_accum = 0.0;
            g_ticket     = 0;
        }
    }
}

// ---------------------------------------------------------------------------
extern "C" void kernel_launch(void* const* d_in, const int* in_sizes, int n_in,
                              void* d_out, int out_size) {
    const float* x       = (const float*)d_in[0];
    const int*   labels  = (const int*)  d_in[1];
    const float* centers = (const float*)d_in[2];

    float* out = (float*)d_out;
    const int centers_elems = NUM_CLASS * DIMS;          // 2,048,000
    float* out_centers = out + (out_size - centers_elems);
    float* out_loss    = (out_size > centers_elems) ? out : nullptr;

    ema_lastidx_kernel<<<(NSAMP + 511) / 512, 512>>>(labels);
    ema_fused_kernel<<<NUM_CLASS + NLOSS_BLOCKS, 256>>>(x, labels, centers,
                                                        out_loss, out_centers);
}